// round 2
// baseline (speedup 1.0000x reference)
#include <cuda_runtime.h>

#define NN 65536
#define NE 1048576
#define F 128

// ---------------- scratch (static device globals; no allocation) ----------------
__device__ float g_bufA[NN * F];
__device__ float g_bufB[NN * F];
__device__ int   g_deg_out[NN];
__device__ int   g_deg_in[NN];
__device__ int   g_cursor[NN];
__device__ int   g_row_ptr[NN + 1];
__device__ int   g_csr_src[NE];
__device__ float g_csr_w[NE];
__device__ float g_out_norm[NN];
__device__ float g_in_norm[NN];

// ---------------- graph preprocessing ----------------
__global__ void k_zero() {
    int i = blockIdx.x * blockDim.x + threadIdx.x;
    if (i < NN) { g_deg_out[i] = 0; g_deg_in[i] = 0; g_cursor[i] = 0; }
}

__global__ void k_hist(const int* __restrict__ src, const int* __restrict__ dst) {
    int i = blockIdx.x * blockDim.x + threadIdx.x;
    if (i < NE) {
        atomicAdd(&g_deg_out[src[i]], 1);
        atomicAdd(&g_deg_in[dst[i]], 1);
    }
}

__global__ void k_norm() {
    int i = blockIdx.x * blockDim.x + threadIdx.x;
    if (i < NN) {
        g_out_norm[i] = rsqrtf((float)max(g_deg_out[i], 1));
        g_in_norm[i]  = rsqrtf((float)max(g_deg_in[i], 1));
    }
}

// exclusive scan of g_deg_in into g_row_ptr; single block of 1024 threads,
// each thread owns 64 contiguous elements (two-pass).
__global__ void k_scan() {
    int t = threadIdx.x;
    int base = t * 64;
    int sum = 0;
    for (int i = 0; i < 64; i++) sum += g_deg_in[base + i];
    __shared__ int s[1024];
    s[t] = sum;
    __syncthreads();
    for (int off = 1; off < 1024; off <<= 1) {
        int v = 0;
        if (t >= off) v = s[t - off];
        __syncthreads();
        if (t >= off) s[t] += v;
        __syncthreads();
    }
    int run = s[t] - sum;  // exclusive prefix of this thread's chunk
    for (int i = 0; i < 64; i++) {
        int d = g_deg_in[base + i];
        g_row_ptr[base + i] = run;
        run += d;
    }
    if (t == 1023) g_row_ptr[NN] = run;
}

__global__ void k_fill(const int* __restrict__ src, const int* __restrict__ dst,
                       const float* __restrict__ ew) {
    int i = blockIdx.x * blockDim.x + threadIdx.x;
    if (i < NE) {
        int d = dst[i];
        int p = g_row_ptr[d] + atomicAdd(&g_cursor[d], 1);
        g_csr_src[p] = src[i];
        g_csr_w[p]   = ew[i];
    }
}

// ---------------- fused row-scale + SGEMM: C[64xF] = diag(scale) * A @ W ----------------
// block = 256 threads, 64 rows per block. Thread tile 8 rows x 4 cols.
__global__ __launch_bounds__(256) void k_gemm(const float* __restrict__ A,
                                              const float* __restrict__ W,
                                              const float* __restrict__ scale,
                                              float* __restrict__ C) {
    __shared__ __align__(16) float As[16][68];   // [k][row], padded stride 68 (272B, 16B-aligned)
    __shared__ __align__(16) float Ws[16][128];  // [k][n]
    int tid  = threadIdx.x;
    int base = blockIdx.x * 64;
    int colg = (tid & 31) * 4;   // 4 consecutive output cols
    int rowg = (tid >> 5) * 8;   // 8 consecutive output rows
    int lr = tid >> 2;           // row this thread loads (0..63)
    int lc = (tid & 3) * 4;      // k-offset this thread loads (0,4,8,12)
    float sc = scale[base + lr];

    float acc[8][4];
#pragma unroll
    for (int r = 0; r < 8; r++)
#pragma unroll
        for (int c = 0; c < 4; c++) acc[r][c] = 0.f;

    for (int kk = 0; kk < F; kk += 16) {
        float4 a = *(const float4*)&A[(base + lr) * F + kk + lc];
        As[lc + 0][lr] = a.x * sc;
        As[lc + 1][lr] = a.y * sc;
        As[lc + 2][lr] = a.z * sc;
        As[lc + 3][lr] = a.w * sc;
        {
            int f = tid;
            *(float4*)&Ws[f >> 5][(f & 31) * 4] =
                *(const float4*)&W[(kk + (f >> 5)) * F + (f & 31) * 4];
        }
        {
            int f = tid + 256;
            *(float4*)&Ws[f >> 5][(f & 31) * 4] =
                *(const float4*)&W[(kk + (f >> 5)) * F + (f & 31) * 4];
        }
        __syncthreads();
#pragma unroll
        for (int k = 0; k < 16; k++) {
            float4 b  = *(const float4*)&Ws[k][colg];
            float4 a0 = *(const float4*)&As[k][rowg];
            float4 a1 = *(const float4*)&As[k][rowg + 4];
            float ar[8] = {a0.x, a0.y, a0.z, a0.w, a1.x, a1.y, a1.z, a1.w};
#pragma unroll
            for (int r = 0; r < 8; r++) {
                acc[r][0] += ar[r] * b.x;
                acc[r][1] += ar[r] * b.y;
                acc[r][2] += ar[r] * b.z;
                acc[r][3] += ar[r] * b.w;
            }
        }
        __syncthreads();
    }
#pragma unroll
    for (int r = 0; r < 8; r++) {
        *(float4*)&C[(base + rowg + r) * F + colg] =
            make_float4(acc[r][0], acc[r][1], acc[r][2], acc[r][3]);
    }
}

// ---------------- CSR aggregation: one warp per dst node ----------------
// MODE 0: out = relu(acc * in_norm + bias)
// MODE 1: out = acc * in_norm + bias
// MODE 2: out = sum(w_e * H[src_e])          (final u_mul_e pass)
template <int MODE>
__global__ __launch_bounds__(256) void k_agg(const float* __restrict__ H,
                                             const float* __restrict__ bias,
                                             float* __restrict__ out) {
    int gw   = (blockIdx.x * blockDim.x + threadIdx.x) >> 5;  // node id
    int lane = threadIdx.x & 31;
    int wl   = threadIdx.x >> 5;
    __shared__ int   sh_idx[8][32];
    __shared__ float sh_w[8][32];
    if (gw >= NN) return;

    int beg = g_row_ptr[gw];
    int end = g_row_ptr[gw + 1];
    float4 acc = make_float4(0.f, 0.f, 0.f, 0.f);

    for (int e = beg; e < end;) {
        int n = min(32, end - e);
        sh_idx[wl][lane] = (lane < n) ? g_csr_src[e + lane] : 0;
        if (MODE == 2) sh_w[wl][lane] = (lane < n) ? g_csr_w[e + lane] : 0.f;
        __syncwarp();
#pragma unroll 4
        for (int j = 0; j < n; j++) {
            int s = sh_idx[wl][j];
            float4 x = *(const float4*)&H[s * F + lane * 4];
            if (MODE == 2) {
                float w = sh_w[wl][j];
                acc.x += w * x.x; acc.y += w * x.y;
                acc.z += w * x.z; acc.w += w * x.w;
            } else {
                acc.x += x.x; acc.y += x.y; acc.z += x.z; acc.w += x.w;
            }
        }
        __syncwarp();
        e += n;
    }

    if (MODE != 2) {
        float nrm = g_in_norm[gw];
        float4 b  = *(const float4*)&bias[lane * 4];
        acc.x = acc.x * nrm + b.x;
        acc.y = acc.y * nrm + b.y;
        acc.z = acc.z * nrm + b.z;
        acc.w = acc.w * nrm + b.w;
        if (MODE == 0) {
            acc.x = fmaxf(acc.x, 0.f); acc.y = fmaxf(acc.y, 0.f);
            acc.z = fmaxf(acc.z, 0.f); acc.w = fmaxf(acc.w, 0.f);
        }
    }
    *(float4*)&out[gw * F + lane * 4] = acc;
}

// ---------------- launch ----------------
extern "C" void kernel_launch(void* const* d_in, const int* in_sizes, int n_in,
                              void* d_out, int out_size) {
    const float* feat = (const float*)d_in[0];
    const float* ew   = (const float*)d_in[1];
    const float* W1   = (const float*)d_in[2];
    const float* b1   = (const float*)d_in[3];
    const float* W2   = (const float*)d_in[4];
    const float* b2   = (const float*)d_in[5];
    const int*   src  = (const int*)d_in[6];
    const int*   dst  = (const int*)d_in[7];
    float* out = (float*)d_out;

    float *pA, *pB, *pOutNorm;
    cudaGetSymbolAddress((void**)&pA, g_bufA);
    cudaGetSymbolAddress((void**)&pB, g_bufB);
    cudaGetSymbolAddress((void**)&pOutNorm, g_out_norm);

    k_zero<<<NN / 256, 256>>>();
    k_hist<<<NE / 256, 256>>>(src, dst);
    k_norm<<<NN / 256, 256>>>();
    k_scan<<<1, 1024>>>();
    k_fill<<<NE / 256, 256>>>(src, dst, ew);

    // layer 1: bufA = (feat * out_norm) @ W1 ; bufB = relu(agg * in_norm + b1)
    k_gemm<<<NN / 64, 256>>>(feat, W1, pOutNorm, pA);
    k_agg<0><<<(NN * 32) / 256, 256>>>(pA, b1, pB);

    // layer 2: bufA = (bufB * out_norm) @ W2 ; bufB = agg * in_norm + b2
    k_gemm<<<NN / 64, 256>>>(pB, W2, pOutNorm, pA);
    k_agg<1><<<(NN * 32) / 256, 256>>>(pA, b2, pB);

    // final: out = segment_sum(bufB[src] * eweight, dst)
    k_agg<2><<<(NN * 32) / 256, 256>>>(pB, nullptr, out);
}

// round 3
// speedup vs baseline: 1.4510x; 1.4510x over previous
#include <cuda_runtime.h>

#define NN 65536
#define NE 1048576
#define F 128

// ---------------- scratch (static device globals; no allocation) ----------------
__device__ float g_bufA[NN * F];
__device__ float g_bufB[NN * F];
__device__ int   g_deg_out[NN];
__device__ int   g_deg_in[NN];
__device__ int   g_cursor[NN];
__device__ int   g_row_ptr[NN + 1];
__device__ int   g_csr_src[NE];
__device__ float g_csr_w[NE];
__device__ float g_out_norm[NN];
__device__ float g_in_norm[NN];
__device__ int   g_blocksum[64];
__device__ int   g_blockoff[64];

// ---------------- graph preprocessing ----------------
__global__ void k_zero() {
    int i = blockIdx.x * blockDim.x + threadIdx.x;
    if (i < NN) { g_deg_out[i] = 0; g_deg_in[i] = 0; g_cursor[i] = 0; }
}

__global__ void k_hist(const int* __restrict__ src, const int* __restrict__ dst) {
    int i = blockIdx.x * blockDim.x + threadIdx.x;
    if (i < NE) {
        atomicAdd(&g_deg_out[src[i]], 1);
        atomicAdd(&g_deg_in[dst[i]], 1);
    }
}

__global__ void k_norm() {
    int i = blockIdx.x * blockDim.x + threadIdx.x;
    if (i < NN) {
        g_out_norm[i] = rsqrtf((float)max(g_deg_out[i], 1));
        g_in_norm[i]  = rsqrtf((float)max(g_deg_in[i], 1));
    }
}

// ---------------- hierarchical exclusive scan of g_deg_in -> g_row_ptr ----------------
// phase 1: 64 blocks x 1024 threads, 1 element/thread. Warp shfl-scan + block scan.
__global__ __launch_bounds__(1024) void k_scan1() {
    int i = blockIdx.x * 1024 + threadIdx.x;
    int lane = threadIdx.x & 31;
    int w    = threadIdx.x >> 5;
    int d = g_deg_in[i];
    int v = d;  // inclusive scan value
#pragma unroll
    for (int off = 1; off < 32; off <<= 1) {
        int t = __shfl_up_sync(0xFFFFFFFFu, v, off);
        if (lane >= off) v += t;
    }
    __shared__ int ws[32];
    if (lane == 31) ws[w] = v;
    __syncthreads();
    if (w == 0) {
        int s = ws[lane];
#pragma unroll
        for (int off = 1; off < 32; off <<= 1) {
            int t = __shfl_up_sync(0xFFFFFFFFu, s, off);
            if (lane >= off) s += t;
        }
        ws[lane] = s;  // inclusive scan of warp sums
    }
    __syncthreads();
    int warp_off = (w > 0) ? ws[w - 1] : 0;
    g_row_ptr[i] = v - d + warp_off;               // block-local exclusive prefix
    if (threadIdx.x == 1023) g_blocksum[blockIdx.x] = ws[31];  // block total
}

// phase 2: scan the 64 block sums (2 warps + smem bridge)
__global__ void k_scan2() {
    int t = threadIdx.x;  // 64 threads
    int lane = t & 31;
    int w    = t >> 5;
    int d = g_blocksum[t];
    int v = d;
#pragma unroll
    for (int off = 1; off < 32; off <<= 1) {
        int x = __shfl_up_sync(0xFFFFFFFFu, v, off);
        if (lane >= off) v += x;
    }
    __shared__ int s0;
    if (t == 31) s0 = v;
    __syncthreads();
    g_blockoff[t] = v - d + (w ? s0 : 0);
}

// phase 3: add block offsets; total edge count is the constant NE
__global__ __launch_bounds__(1024) void k_scan3() {
    int i = blockIdx.x * 1024 + threadIdx.x;
    g_row_ptr[i] += g_blockoff[blockIdx.x];
    if (i == 0) g_row_ptr[NN] = NE;
}

__global__ void k_fill(const int* __restrict__ src, const int* __restrict__ dst,
                       const float* __restrict__ ew) {
    int i = blockIdx.x * blockDim.x + threadIdx.x;
    if (i < NE) {
        int d = dst[i];
        int p = g_row_ptr[d] + atomicAdd(&g_cursor[d], 1);
        g_csr_src[p] = src[i];
        g_csr_w[p]   = ew[i];
    }
}

// ---------------- fused row-scale + SGEMM: C[64xF] = diag(scale) * A @ W ----------------
// block = 256 threads, 64 rows per block. Thread tile 8 rows x 4 cols.
__global__ __launch_bounds__(256) void k_gemm(const float* __restrict__ A,
                                              const float* __restrict__ W,
                                              const float* __restrict__ scale,
                                              float* __restrict__ C) {
    __shared__ __align__(16) float As[16][68];   // [k][row], padded stride 68
    __shared__ __align__(16) float Ws[16][128];  // [k][n]
    int tid  = threadIdx.x;
    int base = blockIdx.x * 64;
    int colg = (tid & 31) * 4;   // 4 consecutive output cols
    int rowg = (tid >> 5) * 8;   // 8 consecutive output rows
    int lr = tid >> 2;           // row this thread loads (0..63)
    int lc = (tid & 3) * 4;      // k-offset this thread loads (0,4,8,12)
    float sc = scale[base + lr];

    float acc[8][4];
#pragma unroll
    for (int r = 0; r < 8; r++)
#pragma unroll
        for (int c = 0; c < 4; c++) acc[r][c] = 0.f;

    for (int kk = 0; kk < F; kk += 16) {
        float4 a = *(const float4*)&A[(base + lr) * F + kk + lc];
        As[lc + 0][lr] = a.x * sc;
        As[lc + 1][lr] = a.y * sc;
        As[lc + 2][lr] = a.z * sc;
        As[lc + 3][lr] = a.w * sc;
        {
            int f = tid;
            *(float4*)&Ws[f >> 5][(f & 31) * 4] =
                *(const float4*)&W[(kk + (f >> 5)) * F + (f & 31) * 4];
        }
        {
            int f = tid + 256;
            *(float4*)&Ws[f >> 5][(f & 31) * 4] =
                *(const float4*)&W[(kk + (f >> 5)) * F + (f & 31) * 4];
        }
        __syncthreads();
#pragma unroll
        for (int k = 0; k < 16; k++) {
            float4 b  = *(const float4*)&Ws[k][colg];
            float4 a0 = *(const float4*)&As[k][rowg];
            float4 a1 = *(const float4*)&As[k][rowg + 4];
            float ar[8] = {a0.x, a0.y, a0.z, a0.w, a1.x, a1.y, a1.z, a1.w};
#pragma unroll
            for (int r = 0; r < 8; r++) {
                acc[r][0] += ar[r] * b.x;
                acc[r][1] += ar[r] * b.y;
                acc[r][2] += ar[r] * b.z;
                acc[r][3] += ar[r] * b.w;
            }
        }
        __syncthreads();
    }
#pragma unroll
    for (int r = 0; r < 8; r++) {
        *(float4*)&C[(base + rowg + r) * F + colg] =
            make_float4(acc[r][0], acc[r][1], acc[r][2], acc[r][3]);
    }
}

// ---------------- CSR aggregation: one warp per dst node ----------------
// MODE 0: out = relu(acc * in_norm + bias)
// MODE 1: out = acc * in_norm + bias
// MODE 2: out = sum(w_e * H[src_e])          (final u_mul_e pass)
template <int MODE>
__global__ __launch_bounds__(256) void k_agg(const float* __restrict__ H,
                                             const float* __restrict__ bias,
                                             float* __restrict__ out) {
    int gw   = (blockIdx.x * blockDim.x + threadIdx.x) >> 5;  // node id
    int lane = threadIdx.x & 31;
    int wl   = threadIdx.x >> 5;
    __shared__ int   sh_idx[8][32];
    __shared__ float sh_w[8][32];
    if (gw >= NN) return;

    int beg = g_row_ptr[gw];
    int end = g_row_ptr[gw + 1];
    float4 acc = make_float4(0.f, 0.f, 0.f, 0.f);

    for (int e = beg; e < end;) {
        int n = min(32, end - e);
        sh_idx[wl][lane] = (lane < n) ? g_csr_src[e + lane] : 0;
        if (MODE == 2) sh_w[wl][lane] = (lane < n) ? g_csr_w[e + lane] : 0.f;
        __syncwarp();
#pragma unroll 4
        for (int j = 0; j < n; j++) {
            int s = sh_idx[wl][j];
            float4 x = *(const float4*)&H[s * F + lane * 4];
            if (MODE == 2) {
                float w = sh_w[wl][j];
                acc.x += w * x.x; acc.y += w * x.y;
                acc.z += w * x.z; acc.w += w * x.w;
            } else {
                acc.x += x.x; acc.y += x.y; acc.z += x.z; acc.w += x.w;
            }
        }
        __syncwarp();
        e += n;
    }

    if (MODE != 2) {
        float nrm = g_in_norm[gw];
        float4 b  = *(const float4*)&bias[lane * 4];
        acc.x = acc.x * nrm + b.x;
        acc.y = acc.y * nrm + b.y;
        acc.z = acc.z * nrm + b.z;
        acc.w = acc.w * nrm + b.w;
        if (MODE == 0) {
            acc.x = fmaxf(acc.x, 0.f); acc.y = fmaxf(acc.y, 0.f);
            acc.z = fmaxf(acc.z, 0.f); acc.w = fmaxf(acc.w, 0.f);
        }
    }
    *(float4*)&out[gw * F + lane * 4] = acc;
}

// ---------------- launch ----------------
extern "C" void kernel_launch(void* const* d_in, const int* in_sizes, int n_in,
                              void* d_out, int out_size) {
    const float* feat = (const float*)d_in[0];
    const float* ew   = (const float*)d_in[1];
    const float* W1   = (const float*)d_in[2];
    const float* b1   = (const float*)d_in[3];
    const float* W2   = (const float*)d_in[4];
    const float* b2   = (const float*)d_in[5];
    const int*   src  = (const int*)d_in[6];
    const int*   dst  = (const int*)d_in[7];
    float* out = (float*)d_out;

    float *pA, *pB, *pOutNorm;
    cudaGetSymbolAddress((void**)&pA, g_bufA);
    cudaGetSymbolAddress((void**)&pB, g_bufB);
    cudaGetSymbolAddress((void**)&pOutNorm, g_out_norm);

    k_zero<<<NN / 256, 256>>>();
    k_hist<<<NE / 256, 256>>>(src, dst);
    k_norm<<<NN / 256, 256>>>();
    k_scan1<<<64, 1024>>>();
    k_scan2<<<1, 64>>>();
    k_scan3<<<64, 1024>>>();
    k_fill<<<NE / 256, 256>>>(src, dst, ew);

    // layer 1: bufA = (feat * out_norm) @ W1 ; bufB = relu(agg * in_norm + b1)
    k_gemm<<<NN / 64, 256>>>(feat, W1, pOutNorm, pA);
    k_agg<0><<<(NN * 32) / 256, 256>>>(pA, b1, pB);

    // layer 2: bufA = (bufB * out_norm) @ W2 ; bufB = agg * in_norm + b2
    k_gemm<<<NN / 64, 256>>>(pB, W2, pOutNorm, pA);
    k_agg<1><<<(NN * 32) / 256, 256>>>(pA, b2, pB);

    // final: out = segment_sum(bufB[src] * eweight, dst)
    k_agg<2><<<(NN * 32) / 256, 256>>>(pB, nullptr, out);
}

// round 6
// speedup vs baseline: 1.7753x; 1.2235x over previous
#include <cuda_runtime.h>
#include <cstdint>

#define NN 65536
#define NE 1048576
#define F 128

// ---------------- scratch (static device globals; no allocation) ----------------
__device__ float g_bufA[NN * F];
__device__ float g_bufB[NN * F];
__device__ int   g_deg_out[NN];
__device__ int   g_deg_in[NN];
__device__ int   g_cursor[NN];
__device__ int   g_row_ptr[NN + 1];
__device__ int   g_csr_src[NE];
__device__ float g_csr_w[NE];
__device__ float g_out_norm[NN];
__device__ float g_in_norm[NN];
__device__ int   g_blocksum[64];
__device__ int   g_blockoff[64];

__device__ __forceinline__ uint32_t f2tf32(float f) {
    uint32_t r;
    asm("cvt.rna.tf32.f32 %0, %1;" : "=r"(r) : "f"(f));
    return r;
}

// ---------------- graph preprocessing ----------------
__global__ void k_zero() {
    int i = blockIdx.x * blockDim.x + threadIdx.x;
    if (i < NN) { g_deg_out[i] = 0; g_deg_in[i] = 0; g_cursor[i] = 0; }
}

__global__ void k_hist(const int* __restrict__ src, const int* __restrict__ dst) {
    int i = blockIdx.x * blockDim.x + threadIdx.x;
    if (i < NE) {
        atomicAdd(&g_deg_out[src[i]], 1);
        atomicAdd(&g_deg_in[dst[i]], 1);
    }
}

__global__ void k_norm() {
    int i = blockIdx.x * blockDim.x + threadIdx.x;
    if (i < NN) {
        g_out_norm[i] = rsqrtf((float)max(g_deg_out[i], 1));
        g_in_norm[i]  = rsqrtf((float)max(g_deg_in[i], 1));
    }
}

// hierarchical exclusive scan of g_deg_in -> g_row_ptr
__global__ __launch_bounds__(1024) void k_scan1() {
    int i = blockIdx.x * 1024 + threadIdx.x;
    int lane = threadIdx.x & 31;
    int w    = threadIdx.x >> 5;
    int d = g_deg_in[i];
    int v = d;
#pragma unroll
    for (int off = 1; off < 32; off <<= 1) {
        int t = __shfl_up_sync(0xFFFFFFFFu, v, off);
        if (lane >= off) v += t;
    }
    __shared__ int ws[32];
    if (lane == 31) ws[w] = v;
    __syncthreads();
    if (w == 0) {
        int s = ws[lane];
#pragma unroll
        for (int off = 1; off < 32; off <<= 1) {
            int t = __shfl_up_sync(0xFFFFFFFFu, s, off);
            if (lane >= off) s += t;
        }
        ws[lane] = s;
    }
    __syncthreads();
    int warp_off = (w > 0) ? ws[w - 1] : 0;
    g_row_ptr[i] = v - d + warp_off;
    if (threadIdx.x == 1023) g_blocksum[blockIdx.x] = ws[31];
}

__global__ void k_scan2() {
    int t = threadIdx.x;
    int lane = t & 31;
    int w    = t >> 5;
    int d = g_blocksum[t];
    int v = d;
#pragma unroll
    for (int off = 1; off < 32; off <<= 1) {
        int x = __shfl_up_sync(0xFFFFFFFFu, v, off);
        if (lane >= off) v += x;
    }
    __shared__ int s0;
    if (t == 31) s0 = v;
    __syncthreads();
    g_blockoff[t] = v - d + (w ? s0 : 0);
}

__global__ __launch_bounds__(1024) void k_scan3() {
    int i = blockIdx.x * 1024 + threadIdx.x;
    g_row_ptr[i] += g_blockoff[blockIdx.x];
    if (i == 0) g_row_ptr[NN] = NE;
}

__global__ void k_fill(const int* __restrict__ src, const int* __restrict__ dst,
                       const float* __restrict__ ew) {
    int i = blockIdx.x * blockDim.x + threadIdx.x;
    if (i < NE) {
        int d = dst[i];
        int p = g_row_ptr[d] + atomicAdd(&g_cursor[d], 1);
        g_csr_src[p] = src[i];
        g_csr_w[p]   = ew[i];
    }
}

// ---------------- TF32 mma.sync GEMM: C[128 x 128] = (diag(scale)*A) @ W ----------------
// Block 256 thr (8 warps, 4m x 2n). Warp tile 32x64 = 2x8 m16n8k8 fragments.
// A smem [128][132] (stride 132: frag banks 4*grp+tig all distinct)
// B smem [128][136] = W[k][n] direct (stride 136: frag banks 8*tig+grp all distinct)
#define SA_STRIDE 132
#define SB_STRIDE 136
#define SM_B_OFF (128 * SA_STRIDE)           // in floats
#define SMEM_MMA ((128 * SA_STRIDE + 128 * SB_STRIDE) * 4)

__global__ __launch_bounds__(256) void k_gemm_mma(const float* __restrict__ A,
                                                  const float* __restrict__ W,
                                                  const float* __restrict__ scale,
                                                  float* __restrict__ C) {
    extern __shared__ uint32_t sm[];
    uint32_t* sA = sm;
    uint32_t* sB = sm + SM_B_OFF;
    int tid  = threadIdx.x;
    int wid  = tid >> 5;
    int lane = tid & 31;
    int base = blockIdx.x * 128;

    // fill A (row-scaled, tf32) and B = W (tf32)
#pragma unroll
    for (int it = 0; it < 16; it++) {
        int idx = it * 256 + tid;
        int row = idx >> 5, c4 = (idx & 31) << 2;
        float sc = scale[base + row];
        float4 a = *(const float4*)&A[(base + row) * F + c4];
        uint4 t;
        t.x = f2tf32(a.x * sc); t.y = f2tf32(a.y * sc);
        t.z = f2tf32(a.z * sc); t.w = f2tf32(a.w * sc);
        *(uint4*)&sA[row * SA_STRIDE + c4] = t;

        float4 b = *(const float4*)&W[idx * 4];
        uint4 u;
        u.x = f2tf32(b.x); u.y = f2tf32(b.y);
        u.z = f2tf32(b.z); u.w = f2tf32(b.w);
        *(uint4*)&sB[row * SB_STRIDE + c4] = u;
    }
    __syncthreads();

    int grp = lane >> 2, tig = lane & 3;
    int wr = (wid & 3) * 32;   // warp m-base within tile
    int wc = (wid >> 2) * 64;  // warp n-base within tile

    float c[2][8][4];
#pragma unroll
    for (int mt = 0; mt < 2; mt++)
#pragma unroll
        for (int nt = 0; nt < 8; nt++)
#pragma unroll
            for (int j = 0; j < 4; j++) c[mt][nt][j] = 0.f;

#pragma unroll
    for (int k8 = 0; k8 < 128; k8 += 8) {
        uint32_t af[2][4];
#pragma unroll
        for (int mt = 0; mt < 2; mt++) {
            int r0 = wr + mt * 16 + grp;
            af[mt][0] = sA[r0 * SA_STRIDE + k8 + tig];
            af[mt][1] = sA[(r0 + 8) * SA_STRIDE + k8 + tig];
            af[mt][2] = sA[r0 * SA_STRIDE + k8 + tig + 4];
            af[mt][3] = sA[(r0 + 8) * SA_STRIDE + k8 + tig + 4];
        }
        uint32_t bf[8][2];
#pragma unroll
        for (int nt = 0; nt < 8; nt++) {
            int nb = wc + nt * 8 + grp;
            bf[nt][0] = sB[(k8 + tig) * SB_STRIDE + nb];
            bf[nt][1] = sB[(k8 + tig + 4) * SB_STRIDE + nb];
        }
#pragma unroll
        for (int mt = 0; mt < 2; mt++)
#pragma unroll
            for (int nt = 0; nt < 8; nt++) {
                asm volatile(
                    "mma.sync.aligned.m16n8k8.row.col.f32.tf32.tf32.f32 "
                    "{%0,%1,%2,%3}, {%4,%5,%6,%7}, {%8,%9}, {%0,%1,%2,%3};"
                    : "+f"(c[mt][nt][0]), "+f"(c[mt][nt][1]),
                      "+f"(c[mt][nt][2]), "+f"(c[mt][nt][3])
                    : "r"(af[mt][0]), "r"(af[mt][1]), "r"(af[mt][2]), "r"(af[mt][3]),
                      "r"(bf[nt][0]), "r"(bf[nt][1]));
            }
    }

    // epilogue: c0,c1 -> (row, 2tig..+1); c2,c3 -> (row+8, ..)
#pragma unroll
    for (int mt = 0; mt < 2; mt++) {
        int r0 = base + wr + mt * 16 + grp;
#pragma unroll
        for (int nt = 0; nt < 8; nt++) {
            int cb = wc + nt * 8 + tig * 2;
            *(float2*)&C[r0 * F + cb]       = make_float2(c[mt][nt][0], c[mt][nt][1]);
            *(float2*)&C[(r0 + 8) * F + cb] = make_float2(c[mt][nt][2], c[mt][nt][3]);
        }
    }
}

// ---------------- CSR aggregation: one warp per dst node ----------------
template <int MODE>
__global__ __launch_bounds__(256) void k_agg(const float* __restrict__ H,
                                             const float* __restrict__ bias,
                                             float* __restrict__ out) {
    int gw   = (blockIdx.x * blockDim.x + threadIdx.x) >> 5;
    int lane = threadIdx.x & 31;
    int wl   = threadIdx.x >> 5;
    __shared__ int   sh_idx[8][32];
    __shared__ float sh_w[8][32];
    if (gw >= NN) return;

    int beg = g_row_ptr[gw];
    int end = g_row_ptr[gw + 1];
    float4 acc = make_float4(0.f, 0.f, 0.f, 0.f);

    for (int e = beg; e < end;) {
        int n = min(32, end - e);
        sh_idx[wl][lane] = (lane < n) ? g_csr_src[e + lane] : 0;
        if (MODE == 2) sh_w[wl][lane] = (lane < n) ? g_csr_w[e + lane] : 0.f;
        __syncwarp();
#pragma unroll 4
        for (int j = 0; j < n; j++) {
            int s = sh_idx[wl][j];
            float4 x = *(const float4*)&H[s * F + lane * 4];
            if (MODE == 2) {
                float w = sh_w[wl][j];
                acc.x += w * x.x; acc.y += w * x.y;
                acc.z += w * x.z; acc.w += w * x.w;
            } else {
                acc.x += x.x; acc.y += x.y; acc.z += x.z; acc.w += x.w;
            }
        }
        __syncwarp();
        e += n;
    }

    if (MODE != 2) {
        float nrm = g_in_norm[gw];
        float4 b  = *(const float4*)&bias[lane * 4];
        acc.x = acc.x * nrm + b.x;
        acc.y = acc.y * nrm + b.y;
        acc.z = acc.z * nrm + b.z;
        acc.w = acc.w * nrm + b.w;
        if (MODE == 0) {
            acc.x = fmaxf(acc.x, 0.f); acc.y = fmaxf(acc.y, 0.f);
            acc.z = fmaxf(acc.z, 0.f); acc.w = fmaxf(acc.w, 0.f);
        }
    }
    *(float4*)&out[gw * F + lane * 4] = acc;
}

// ---------------- launch ----------------
extern "C" void kernel_launch(void* const* d_in, const int* in_sizes, int n_in,
                              void* d_out, int out_size) {
    const float* feat = (const float*)d_in[0];
    const float* ew   = (const float*)d_in[1];
    const float* W1   = (const float*)d_in[2];
    const float* b1   = (const float*)d_in[3];
    const float* W2   = (const float*)d_in[4];
    const float* b2   = (const float*)d_in[5];
    const int*   src  = (const int*)d_in[6];
    const int*   dst  = (const int*)d_in[7];
    float* out = (float*)d_out;

    float *pA, *pB, *pOutNorm;
    cudaGetSymbolAddress((void**)&pA, g_bufA);
    cudaGetSymbolAddress((void**)&pB, g_bufB);
    cudaGetSymbolAddress((void**)&pOutNorm, g_out_norm);

    static bool attr_done = false;
    if (!attr_done) {
        cudaFuncSetAttribute(k_gemm_mma, cudaFuncAttributeMaxDynamicSharedMemorySize, SMEM_MMA);
        attr_done = true;
    }

    k_zero<<<NN / 256, 256>>>();
    k_hist<<<NE / 256, 256>>>(src, dst);
    k_norm<<<NN / 256, 256>>>();
    k_scan1<<<64, 1024>>>();
    k_scan2<<<1, 64>>>();
    k_scan3<<<64, 1024>>>();
    k_fill<<<NE / 256, 256>>>(src, dst, ew);

    // layer 1
    k_gemm_mma<<<NN / 128, 256, SMEM_MMA>>>(feat, W1, pOutNorm, pA);
    k_agg<0><<<(NN * 32) / 256, 256>>>(pA, b1, pB);

    // layer 2
    k_gemm_mma<<<NN / 128, 256, SMEM_MMA>>>(pB, W2, pOutNorm, pA);
    k_agg<1><<<(NN * 32) / 256, 256>>>(pA, b2, pB);

    // final: out = segment_sum(bufB[src] * eweight, dst)
    k_agg<2><<<(NN * 32) / 256, 256>>>(pB, nullptr, out);
}